// round 2
// baseline (speedup 1.0000x reference)
#include <cuda_runtime.h>
#include <cuda_bf16.h>
#include <cstddef>

// Problem constants
#define BATCH 2
#define SEQ 2048
#define HID 2048
#define KVSZ 512
#define HEADS 32
#define HD 64
#define MTOK (BATCH*SEQ)   // 4096 rows

// Scratch (device globals: allocation-free)
__device__ float g_q[(size_t)MTOK * HID];     // 33.5 MB
__device__ float g_k[(size_t)MTOK * KVSZ];    //  8.4 MB
__device__ float g_v[(size_t)MTOK * KVSZ];    //  8.4 MB
__device__ float g_ao[(size_t)MTOK * HID];    // 33.5 MB

// ---------------------------------------------------------------------------
// SGEMM + bias: C[M,N] = A[M,K] @ B[K,N] + bias[N]
// BM=BN=64, BK=16, 256 threads, 4x4 per-thread tile.
// ---------------------------------------------------------------------------
__global__ __launch_bounds__(256)
void sgemm_bias(const float* __restrict__ A, const float* __restrict__ B,
                const float* __restrict__ bias, float* __restrict__ C,
                int M, int N, int K) {
    const int BM = 64, BN = 64, BK = 16;
    __shared__ float As[BK][BM + 4];   // row = 68 floats = 17*16B (float4-aligned)
    __shared__ float Bs[BK][BN + 4];

    int tid = threadIdx.x;
    int tx = tid & 15;        // 0..15 -> N
    int ty = tid >> 4;        // 0..15 -> M
    int row0 = blockIdx.y * BM;
    int col0 = blockIdx.x * BN;

    // A-tile load mapping: 64 rows x 16 k  (one float4 per thread)
    int a_row = tid >> 2;            // 0..63
    int a_k4  = (tid & 3) << 2;      // 0,4,8,12
    // B-tile load mapping: 16 k x 64 cols (one float4 per thread)
    int b_kk  = tid >> 4;            // 0..15
    int b_c4  = (tid & 15) << 2;     // 0..60

    float acc[4][4];
#pragma unroll
    for (int i = 0; i < 4; i++)
#pragma unroll
        for (int j = 0; j < 4; j++) acc[i][j] = 0.f;

    const float* Ap = A + (size_t)(row0 + a_row) * K + a_k4;
    const float* Bp = B + (size_t)b_kk * N + col0 + b_c4;

    for (int k0 = 0; k0 < K; k0 += BK) {
        float4 av = *(const float4*)(Ap + k0);
        As[a_k4 + 0][a_row] = av.x;
        As[a_k4 + 1][a_row] = av.y;
        As[a_k4 + 2][a_row] = av.z;
        As[a_k4 + 3][a_row] = av.w;
        *(float4*)&Bs[b_kk][b_c4] = *(const float4*)(Bp + (size_t)k0 * N);
        __syncthreads();
#pragma unroll
        for (int kk = 0; kk < BK; kk++) {
            float4 a4 = *(const float4*)&As[kk][ty << 2];
            float4 b4 = *(const float4*)&Bs[kk][tx << 2];
            float a[4] = {a4.x, a4.y, a4.z, a4.w};
            float b[4] = {b4.x, b4.y, b4.z, b4.w};
#pragma unroll
            for (int i = 0; i < 4; i++)
#pragma unroll
                for (int j = 0; j < 4; j++) acc[i][j] += a[i] * b[j];
        }
        __syncthreads();
    }

#pragma unroll
    for (int i = 0; i < 4; i++) {
        int r = row0 + (ty << 2) + i;
        float* Cr = C + (size_t)r * N + col0 + (tx << 2);
        const float* br = bias + col0 + (tx << 2);
#pragma unroll
        for (int j = 0; j < 4; j++) Cr[j] = acc[i][j] + br[j];
    }
}

// ---------------------------------------------------------------------------
// Flash attention, fp32. One thread = one q row (BM=128 rows/block).
// K/V tiles of BN=64 rows in smem; online softmax with branch-skipped rescale.
// grid = (SEQ/128, HEADS, BATCH), block = 128
// ---------------------------------------------------------------------------
__global__ __launch_bounds__(128, 2)
void flash_attn(const float* __restrict__ q, const float* __restrict__ k,
                const float* __restrict__ v, const float* __restrict__ mask,
                float* __restrict__ out) {
    const int BN = 64;
    int h = blockIdx.y;                       // 0..31
    int b = blockIdx.z;
    int r = blockIdx.x * 128 + threadIdx.x;   // q row within sequence
    int qcol = h * HD;                        // kv*256 + qpk*64 == h*64
    int kcol = (h >> 2) * HD;                 // kv head columns in K/V

    const float scale = 0.125f;               // 1/sqrt(64)
    float qr[HD];
    {
        const float* qrow = q + ((size_t)b * SEQ + r) * HID + qcol;
#pragma unroll
        for (int d = 0; d < HD; d++) qr[d] = qrow[d] * scale;
    }

    float m = -1e30f, l = 0.f;
    float acc[HD];
#pragma unroll
    for (int d = 0; d < HD; d++) acc[d] = 0.f;

    __shared__ float ks[BN][HD];
    __shared__ float vs[BN][HD];
    __shared__ float ms[BN];

    const float* kbase = k + (size_t)b * SEQ * KVSZ + kcol;
    const float* vbase = v + (size_t)b * SEQ * KVSZ + kcol;
    const float* mbase = mask + (size_t)b * SEQ;

    for (int kt = 0; kt < SEQ; kt += BN) {
        __syncthreads();
        // load K/V tiles: 64x64 floats each, one float4 per thread iteration
        for (int i = threadIdx.x; i < BN * (HD / 4); i += 128) {
            int j  = i >> 4;            // row in tile (HD/4 = 16 float4 per row)
            int d4 = (i & 15) << 2;
            *(float4*)&ks[j][d4] = *(const float4*)&kbase[(size_t)(kt + j) * KVSZ + d4];
            *(float4*)&vs[j][d4] = *(const float4*)&vbase[(size_t)(kt + j) * KVSZ + d4];
        }
        if (threadIdx.x < BN) ms[threadIdx.x] = mbase[kt + threadIdx.x];
        __syncthreads();

        for (int j = 0; j < BN; j++) {
            float s0 = 0.f, s1 = 0.f, s2 = 0.f, s3 = 0.f;
#pragma unroll
            for (int d = 0; d < HD; d += 4) {
                s0 += qr[d + 0] * ks[j][d + 0];
                s1 += qr[d + 1] * ks[j][d + 1];
                s2 += qr[d + 2] * ks[j][d + 2];
                s3 += qr[d + 3] * ks[j][d + 3];
            }
            float s = (s0 + s1) + (s2 + s3) + ms[j];
            if (s <= m) {
                float p = __expf(s - m);
                l += p;
#pragma unroll
                for (int d = 0; d < HD; d++) acc[d] += p * vs[j][d];
            } else {
                float c = __expf(m - s);   // first iter: exp(-huge) = 0
                m = s;
                l = l * c + 1.f;
#pragma unroll
                for (int d = 0; d < HD; d++) acc[d] = acc[d] * c + vs[j][d];
            }
        }
    }

    float inv = 1.f / l;
    float* orow = out + ((size_t)b * SEQ + r) * HID + qcol;
#pragma unroll
    for (int d = 0; d < HD; d++) orow[d] = acc[d] * inv;
}

// ---------------------------------------------------------------------------
extern "C" void kernel_launch(void* const* d_in, const int* in_sizes, int n_in,
                              void* d_out, int out_size) {
    const float* x    = (const float*)d_in[0];
    const float* mask = (const float*)d_in[1];
    const float* Wq   = (const float*)d_in[2];
    const float* bq   = (const float*)d_in[3];
    const float* Wk   = (const float*)d_in[4];
    const float* bk   = (const float*)d_in[5];
    const float* Wv   = (const float*)d_in[6];
    const float* bv   = (const float*)d_in[7];
    const float* Wo   = (const float*)d_in[8];
    const float* bo   = (const float*)d_in[9];
    float* out = (float*)d_out;

    float *q, *k, *v, *ao;
    cudaGetSymbolAddress((void**)&q,  g_q);
    cudaGetSymbolAddress((void**)&k,  g_k);
    cudaGetSymbolAddress((void**)&v,  g_v);
    cudaGetSymbolAddress((void**)&ao, g_ao);

    // Projections
    sgemm_bias<<<dim3(HID / 64, MTOK / 64), 256>>>(x, Wq, bq, q, MTOK, HID, HID);
    sgemm_bias<<<dim3(KVSZ / 64, MTOK / 64), 256>>>(x, Wk, bk, k, MTOK, KVSZ, HID);
    sgemm_bias<<<dim3(KVSZ / 64, MTOK / 64), 256>>>(x, Wv, bv, v, MTOK, KVSZ, HID);

    // Attention
    flash_attn<<<dim3(SEQ / 128, HEADS, BATCH), 128>>>(q, k, v, mask, ao);

    // Output projection
    sgemm_bias<<<dim3(HID / 64, MTOK / 64), 256>>>(ao, Wo, bo, out, MTOK, HID, HID);
}

// round 4
// speedup vs baseline: 1.2800x; 1.2800x over previous
#include <cuda_runtime.h>
#include <cuda_bf16.h>
#include <cstdint>
#include <cstddef>

// Problem constants
#define BATCH 2
#define SEQ 2048
#define HID 2048
#define KVSZ 512
#define HEADS 32
#define HD 64
#define MTOK (BATCH*SEQ)   // 4096 rows

// ---------------------------------------------------------------------------
// Scratch (device globals: allocation-free)
// ---------------------------------------------------------------------------
__device__ float g_q[(size_t)MTOK * HID];
__device__ float g_k[(size_t)MTOK * KVSZ];
__device__ float g_v[(size_t)MTOK * KVSZ];
__device__ float g_ao[(size_t)MTOK * HID];

__device__ __nv_bfloat16 g_xh[(size_t)MTOK * HID];
__device__ __nv_bfloat16 g_xl[(size_t)MTOK * HID];
__device__ __nv_bfloat16 g_aoh[(size_t)MTOK * HID];
__device__ __nv_bfloat16 g_aol[(size_t)MTOK * HID];
// transposed weights [N, K] bf16 hi/lo
__device__ __nv_bfloat16 g_wqh[(size_t)HID * HID];
__device__ __nv_bfloat16 g_wql[(size_t)HID * HID];
__device__ __nv_bfloat16 g_wkh[(size_t)KVSZ * HID];
__device__ __nv_bfloat16 g_wkl[(size_t)KVSZ * HID];
__device__ __nv_bfloat16 g_wvh[(size_t)KVSZ * HID];
__device__ __nv_bfloat16 g_wvl[(size_t)KVSZ * HID];
__device__ __nv_bfloat16 g_woh[(size_t)HID * HID];
__device__ __nv_bfloat16 g_wol[(size_t)HID * HID];

// ---------------------------------------------------------------------------
// Portable PTX helpers (no sm_103a-gated instructions!)
// ---------------------------------------------------------------------------
static __device__ __forceinline__ uint32_t smem_u32(const void* p) {
    uint32_t a;
    asm("{ .reg .u64 t; cvta.to.shared.u64 t, %1; cvt.u32.u64 %0, t; }" : "=r"(a) : "l"(p));
    return a;
}
static __device__ __forceinline__ void cp16(uint32_t dst, const void* src) {
    asm volatile("cp.async.cg.shared.global [%0], [%1], 16;" :: "r"(dst), "l"(src));
}
static __device__ __forceinline__ void ldsm4(uint32_t& r0, uint32_t& r1, uint32_t& r2,
                                             uint32_t& r3, uint32_t addr) {
    asm volatile("ldmatrix.sync.aligned.m8n8.x4.shared.b16 {%0,%1,%2,%3}, [%4];"
                 : "=r"(r0), "=r"(r1), "=r"(r2), "=r"(r3) : "r"(addr));
}
static __device__ __forceinline__ void mma16816(float* c, const uint32_t* a,
                                                const uint32_t* b) {
    asm volatile(
        "mma.sync.aligned.m16n8k16.row.col.f32.bf16.bf16.f32 "
        "{%0,%1,%2,%3}, {%4,%5,%6,%7}, {%8,%9}, {%0,%1,%2,%3};"
        : "+f"(c[0]), "+f"(c[1]), "+f"(c[2]), "+f"(c[3])
        : "r"(a[0]), "r"(a[1]), "r"(a[2]), "r"(a[3]), "r"(b[0]), "r"(b[1]));
}

// ---------------------------------------------------------------------------
// Split conversions: fp32 -> (hi, lo) bf16
// ---------------------------------------------------------------------------
__global__ void __launch_bounds__(256)
split_hl(const float* __restrict__ in, __nv_bfloat16* __restrict__ hi,
         __nv_bfloat16* __restrict__ lo, int n) {
    int i = (blockIdx.x * 256 + threadIdx.x) << 2;
    if (i >= n) return;
    float4 f = *(const float4*)(in + i);
    __nv_bfloat16 h0 = __float2bfloat16(f.x);
    __nv_bfloat16 h1 = __float2bfloat16(f.y);
    __nv_bfloat16 h2 = __float2bfloat16(f.z);
    __nv_bfloat16 h3 = __float2bfloat16(f.w);
    __nv_bfloat16 l0 = __float2bfloat16(f.x - __bfloat162float(h0));
    __nv_bfloat16 l1 = __float2bfloat16(f.y - __bfloat162float(h1));
    __nv_bfloat16 l2 = __float2bfloat16(f.z - __bfloat162float(h2));
    __nv_bfloat16 l3 = __float2bfloat16(f.w - __bfloat162float(h3));
    ushort4 uh = make_ushort4(__bfloat16_as_ushort(h0), __bfloat16_as_ushort(h1),
                              __bfloat16_as_ushort(h2), __bfloat16_as_ushort(h3));
    ushort4 ul = make_ushort4(__bfloat16_as_ushort(l0), __bfloat16_as_ushort(l1),
                              __bfloat16_as_ushort(l2), __bfloat16_as_ushort(l3));
    *(ushort4*)(hi + i) = uh;
    *(ushort4*)(lo + i) = ul;
}

// W [Kd, Nd] fp32 row-major -> th/tl [Nd, Kd] bf16 (transposed)
__global__ void __launch_bounds__(256)
split_transpose(const float* __restrict__ W, __nv_bfloat16* __restrict__ th,
                __nv_bfloat16* __restrict__ tl, int Kd, int Nd) {
    __shared__ float t[32][33];
    int n0 = blockIdx.x << 5, k0 = blockIdx.y << 5;
    int tx = threadIdx.x & 31, ty = threadIdx.x >> 5;  // ty 0..7
#pragma unroll
    for (int r = 0; r < 32; r += 8)
        t[ty + r][tx] = W[(size_t)(k0 + ty + r) * Nd + n0 + tx];
    __syncthreads();
#pragma unroll
    for (int r = 0; r < 32; r += 8) {
        float f = t[tx][ty + r];
        __nv_bfloat16 h = __float2bfloat16(f);
        __nv_bfloat16 l = __float2bfloat16(f - __bfloat162float(h));
        size_t o = (size_t)(n0 + ty + r) * Kd + k0 + tx;
        th[o] = h;
        tl[o] = l;
    }
}

// ---------------------------------------------------------------------------
// HMMA GEMM: C[M,N] = Ah@Bh^T + Ah@Bl^T + Al@Bh^T + bias  (fp32 out)
// A* [M,K] bf16 row-major; B* [N,K] bf16 row-major (W transposed).
// CTA tile 128x128, BK=32, 8 warps (each 64x32), cp.async double buffer.
// Smem rows padded to 80B (32 bf16 + 16B) -> conflict-free ldmatrix.
// ---------------------------------------------------------------------------
#define GBM 128
#define GBN 128
#define ROWB 80                         // bytes per smem row
#define TILEB (128 * ROWB)              // 10240 per matrix tile
#define STAGEB (2 * TILEB)              // A + B per stage

__global__ void __launch_bounds__(256)
gemm_mma(const __nv_bfloat16* __restrict__ Ah, const __nv_bfloat16* __restrict__ Al,
         const __nv_bfloat16* __restrict__ Bh, const __nv_bfloat16* __restrict__ Bl,
         const float* __restrict__ bias, float* __restrict__ C,
         int M, int N, int K)
{
    __shared__ __align__(16) char smem[2 * STAGEB];
    const uint32_t sb = smem_u32(smem);

    const int tid  = threadIdx.x;
    const int wid  = tid >> 5;
    const int lane = tid & 31;
    const int warp_m = (wid & 1) << 6;   // 0 / 64
    const int warp_n = (wid >> 1) << 5;  // 0 / 32 / 64 / 96

    const int row0 = blockIdx.y * GBM;
    const int col0 = blockIdx.x * GBN;

    const int KS = K >> 5;               // k-slabs per pass
    const int NS = 3 * KS;

    // cp.async mapping: 512 A-chunks + 512 B-chunks of 16B, 2 each per thread
    const int c_r  = tid >> 1;           // row 0..127
    const int c_c0 = (tid & 1) << 1;     // chunk 0 or 2

    // ldmatrix per-thread offsets
    const uint32_t a_off = (uint32_t)((warp_m + (lane & 7) + (((lane >> 3) & 1) << 3)) * ROWB
                                      + ((lane >> 4) << 4));            // +16B for k-half
    const uint32_t b_off = (uint32_t)((warp_n + (lane & 7) + ((lane >> 4) << 3)) * ROWB
                                      + (((lane >> 3) & 1) << 4));

    float acc[4][4][4];
#pragma unroll
    for (int i = 0; i < 4; i++)
#pragma unroll
        for (int j = 0; j < 4; j++)
#pragma unroll
            for (int t = 0; t < 4; t++) acc[i][j][t] = 0.f;

    // ---- stage loader ------------------------------------------------------
    auto load_stage = [&](int i, int s) {
        int p  = (i >= 2 * KS) ? 2 : ((i >= KS) ? 1 : 0);
        int kk = (i - p * KS) << 5;
        const __nv_bfloat16* Ag = ((p == 2) ? Al : Ah) + (size_t)row0 * K + kk;
        const __nv_bfloat16* Bg = ((p == 1) ? Bl : Bh) + (size_t)col0 * K + kk;
        uint32_t sa = sb + (uint32_t)s * STAGEB;
        uint32_t sbB = sa + TILEB;
        size_t rowbytes = (size_t)K * 2;
        const char* agc = (const char*)Ag + (size_t)c_r * rowbytes;
        const char* bgc = (const char*)Bg + (size_t)c_r * rowbytes;
        uint32_t so = (uint32_t)(c_r * ROWB + c_c0 * 16);
        cp16(sa  + so,      agc + c_c0 * 16);
        cp16(sa  + so + 16, agc + c_c0 * 16 + 16);
        cp16(sbB + so,      bgc + c_c0 * 16);
        cp16(sbB + so + 16, bgc + c_c0 * 16 + 16);
        asm volatile("cp.async.commit_group;" ::: "memory");
    };

    load_stage(0, 0);

    for (int i = 0; i < NS; i++) {
        int s = i & 1;
        if (i + 1 < NS) {
            load_stage(i + 1, s ^ 1);
            asm volatile("cp.async.wait_group 1;" ::: "memory");
        } else {
            asm volatile("cp.async.wait_group 0;" ::: "memory");
        }
        __syncthreads();

        uint32_t sa  = sb + (uint32_t)s * STAGEB;
        uint32_t sbB = sa + TILEB;
#pragma unroll
        for (int ks = 0; ks < 2; ks++) {          // two k16 steps per BK=32
            uint32_t kb = (uint32_t)(ks << 5);    // 16 halves = 32 bytes
            uint32_t a[4][4], b[4][2];
#pragma unroll
            for (int mt = 0; mt < 4; mt++)
                ldsm4(a[mt][0], a[mt][1], a[mt][2], a[mt][3],
                      sa + a_off + (uint32_t)(mt << 4) * ROWB + kb);
#pragma unroll
            for (int np = 0; np < 2; np++)
                ldsm4(b[2*np][0], b[2*np][1], b[2*np+1][0], b[2*np+1][1],
                      sbB + b_off + (uint32_t)(np << 4) * ROWB + kb);
#pragma unroll
            for (int mt = 0; mt < 4; mt++)
#pragma unroll
                for (int nt = 0; nt < 4; nt++)
                    mma16816(acc[mt][nt], a[mt], b[nt]);
        }
        __syncthreads();
    }

    // ---- epilogue -----------------------------------------------------------
    const int qr = lane >> 2;            // quad row 0..7
    const int qc = (lane & 3) << 1;      // col pair 0,2,4,6
#pragma unroll
    for (int mt = 0; mt < 4; mt++) {
        int r = row0 + warp_m + (mt << 4) + qr;
        float* C0 = C + (size_t)r * N;
        float* C1 = C + (size_t)(r + 8) * N;
#pragma unroll
        for (int nt = 0; nt < 4; nt++) {
            int c = col0 + warp_n + (nt << 3) + qc;
            float b0 = bias[c], b1 = bias[c + 1];
            float2 v0 = make_float2(acc[mt][nt][0] + b0, acc[mt][nt][1] + b1);
            float2 v1 = make_float2(acc[mt][nt][2] + b0, acc[mt][nt][3] + b1);
            *(float2*)(C0 + c) = v0;
            *(float2*)(C1 + c) = v1;
        }
    }
}

// ---------------------------------------------------------------------------
// Flash attention, fp32 (unchanged — passing at rel_err 1.9e-6)
// ---------------------------------------------------------------------------
__global__ __launch_bounds__(128, 2)
void flash_attn(const float* __restrict__ q, const float* __restrict__ k,
                const float* __restrict__ v, const float* __restrict__ mask,
                float* __restrict__ out) {
    const int BN = 64;
    int h = blockIdx.y;
    int b = blockIdx.z;
    int r = blockIdx.x * 128 + threadIdx.x;
    int qcol = h * HD;
    int kcol = (h >> 2) * HD;

    const float scale = 0.125f;
    float qr[HD];
    {
        const float* qrow = q + ((size_t)b * SEQ + r) * HID + qcol;
#pragma unroll
        for (int d = 0; d < HD; d++) qr[d] = qrow[d] * scale;
    }

    float m = -1e30f, l = 0.f;
    float acc[HD];
#pragma unroll
    for (int d = 0; d < HD; d++) acc[d] = 0.f;

    __shared__ float ks[BN][HD];
    __shared__ float vs[BN][HD];
    __shared__ float ms[BN];

    const float* kbase = k + (size_t)b * SEQ * KVSZ + kcol;
    const float* vbase = v + (size_t)b * SEQ * KVSZ + kcol;
    const float* mbase = mask + (size_t)b * SEQ;

    for (int kt = 0; kt < SEQ; kt += BN) {
        __syncthreads();
        for (int i = threadIdx.x; i < BN * (HD / 4); i += 128) {
            int j  = i >> 4;
            int d4 = (i & 15) << 2;
            *(float4*)&ks[j][d4] = *(const float4*)&kbase[(size_t)(kt + j) * KVSZ + d4];
            *(float4*)&vs[j][d4] = *(const float4*)&vbase[(size_t)(kt + j) * KVSZ + d4];
        }
        if (threadIdx.x < BN) ms[threadIdx.x] = mbase[kt + threadIdx.x];
        __syncthreads();

        for (int j = 0; j < BN; j++) {
            float s0 = 0.f, s1 = 0.f, s2 = 0.f, s3 = 0.f;
#pragma unroll
            for (int d = 0; d < HD; d += 4) {
                s0 += qr[d + 0] * ks[j][d + 0];
                s1 += qr[d + 1] * ks[j][d + 1];
                s2 += qr[d + 2] * ks[j][d + 2];
                s3 += qr[d + 3] * ks[j][d + 3];
            }
            float s = (s0 + s1) + (s2 + s3) + ms[j];
            if (s <= m) {
                float p = __expf(s - m);
                l += p;
#pragma unroll
                for (int d = 0; d < HD; d++) acc[d] += p * vs[j][d];
            } else {
                float c = __expf(m - s);
                m = s;
                l = l * c + 1.f;
#pragma unroll
                for (int d = 0; d < HD; d++) acc[d] = acc[d] * c + vs[j][d];
            }
        }
    }

    float inv = 1.f / l;
    float* orow = out + ((size_t)b * SEQ + r) * HID + qcol;
#pragma unroll
    for (int d = 0; d < HD; d++) orow[d] = acc[d] * inv;
}

// ---------------------------------------------------------------------------
extern "C" void kernel_launch(void* const* d_in, const int* in_sizes, int n_in,
                              void* d_out, int out_size) {
    const float* x    = (const float*)d_in[0];
    const float* mask = (const float*)d_in[1];
    const float* Wq   = (const float*)d_in[2];
    const float* bq   = (const float*)d_in[3];
    const float* Wk   = (const float*)d_in[4];
    const float* bk   = (const float*)d_in[5];
    const float* Wv   = (const float*)d_in[6];
    const float* bv   = (const float*)d_in[7];
    const float* Wo   = (const float*)d_in[8];
    const float* bo   = (const float*)d_in[9];
    float* out = (float*)d_out;

    float *q, *k, *v, *ao;
    cudaGetSymbolAddress((void**)&q,  g_q);
    cudaGetSymbolAddress((void**)&k,  g_k);
    cudaGetSymbolAddress((void**)&v,  g_v);
    cudaGetSymbolAddress((void**)&ao, g_ao);
    __nv_bfloat16 *xh, *xl, *aoh, *aol, *wqh, *wql, *wkh, *wkl, *wvh, *wvl, *woh, *wol;
    cudaGetSymbolAddress((void**)&xh,  g_xh);
    cudaGetSymbolAddress((void**)&xl,  g_xl);
    cudaGetSymbolAddress((void**)&aoh, g_aoh);
    cudaGetSymbolAddress((void**)&aol, g_aol);
    cudaGetSymbolAddress((void**)&wqh, g_wqh);
    cudaGetSymbolAddress((void**)&wql, g_wql);
    cudaGetSymbolAddress((void**)&wkh, g_wkh);
    cudaGetSymbolAddress((void**)&wkl, g_wkl);
    cudaGetSymbolAddress((void**)&wvh, g_wvh);
    cudaGetSymbolAddress((void**)&wvl, g_wvl);
    cudaGetSymbolAddress((void**)&woh, g_woh);
    cudaGetSymbolAddress((void**)&wol, g_wol);

    // 1) split inputs / weights to bf16 hi+lo
    {
        int n = MTOK * HID;
        split_hl<<<n / 1024, 256>>>(x, xh, xl, n);
    }
    split_transpose<<<dim3(HID / 32, HID / 32), 256>>>(Wq, wqh, wql, HID, HID);
    split_transpose<<<dim3(KVSZ / 32, HID / 32), 256>>>(Wk, wkh, wkl, HID, KVSZ);
    split_transpose<<<dim3(KVSZ / 32, HID / 32), 256>>>(Wv, wvh, wvl, HID, KVSZ);
    split_transpose<<<dim3(HID / 32, HID / 32), 256>>>(Wo, woh, wol, HID, HID);

    // 2) projections on tensor cores (HMMA)
    gemm_mma<<<dim3(HID / GBN,  MTOK / GBM), 256>>>(xh, xl, wqh, wql, bq, q, MTOK, HID,  HID);
    gemm_mma<<<dim3(KVSZ / GBN, MTOK / GBM), 256>>>(xh, xl, wkh, wkl, bk, k, MTOK, KVSZ, HID);
    gemm_mma<<<dim3(KVSZ / GBN, MTOK / GBM), 256>>>(xh, xl, wvh, wvl, bv, v, MTOK, KVSZ, HID);

    // 3) attention (fp32 SIMT, unchanged)
    flash_attn<<<dim3(SEQ / 128, HEADS, BATCH), 128>>>(q, k, v, mask, ao);

    // 4) output projection
    {
        int n = MTOK * HID;
        split_hl<<<n / 1024, 256>>>(ao, aoh, aol, n);
    }
    gemm_mma<<<dim3(HID / GBN, MTOK / GBM), 256>>>(aoh, aol, woh, wol, bo, out, MTOK, HID, HID);
}